// round 13
// baseline (speedup 1.0000x reference)
#include <cuda_runtime.h>
#include <cuda_fp16.h>
#include <cstdint>

#define D66     66
#define DP      72                 // padded dim (4x k16 + 1x k8)
#define NK      65536
#define NQT     8192
#define SPLITS  9
#define NCHALL  (NK / 64)          // 1024 total chunks
#define CK      64
#define SKW     72                 // smem row pitch (fp16); 144B rows
#define ABYTES  (CK * SKW * 2)     // 9216 = one chunk buffer
#define NBUF    4
#define NGROUPS (CK * 9)           // 576 16B-groups per chunk
#define JMP     11.0f              // fast-path jump tolerance (log2 units)

// static device scratch (no cudaMalloc)
__device__ __align__(16) __half g_xh[(size_t)NK * DP];        // fp16(x)
__device__ __align__(16) __half g_qp[(size_t)2 * NQT * DP];   // L2E*q' hi/lo
__device__ float  g_part[(size_t)SPLITS * NQT * D66];
__device__ float2 g_ml[SPLITS * NQT];

// ---------------- asm helpers ----------------
#define MMA16(dv, av, b0_, b1_)                                             \
    asm volatile("mma.sync.aligned.m16n8k16.row.col.f32.f16.f16.f32 "       \
                 "{%0,%1,%2,%3},{%4,%5,%6,%7},{%8,%9},{%0,%1,%2,%3};"       \
                 : "+f"(dv[0]), "+f"(dv[1]), "+f"(dv[2]), "+f"(dv[3])       \
                 : "r"(av[0]), "r"(av[1]), "r"(av[2]), "r"(av[3]),          \
                   "r"(b0_), "r"(b1_))

#define MMA8(dv, a0_, a1_, b0_)                                             \
    asm volatile("mma.sync.aligned.m16n8k8.row.col.f32.f16.f16.f32 "        \
                 "{%0,%1,%2,%3},{%4,%5},{%6},{%0,%1,%2,%3};"                \
                 : "+f"(dv[0]), "+f"(dv[1]), "+f"(dv[2]), "+f"(dv[3])       \
                 : "r"(a0_), "r"(a1_), "r"(b0_))

#define LDSM4(r0, r1, r2, r3, ad)                                           \
    asm volatile("ldmatrix.sync.aligned.m8n8.x4.shared.b16 {%0,%1,%2,%3},[%4];" \
                 : "=r"(r0), "=r"(r1), "=r"(r2), "=r"(r3) : "r"(ad))

#define LDSM2(r0, r1, ad)                                                   \
    asm volatile("ldmatrix.sync.aligned.m8n8.x2.shared.b16 {%0,%1},[%2];"   \
                 : "=r"(r0), "=r"(r1) : "r"(ad))

#define LDSM4T(r0, r1, r2, r3, ad)                                          \
    asm volatile("ldmatrix.sync.aligned.m8n8.x4.trans.shared.b16 {%0,%1,%2,%3},[%4];" \
                 : "=r"(r0), "=r"(r1), "=r"(r2), "=r"(r3) : "r"(ad))

#define LDSM2T(r0, r1, ad)                                                  \
    asm volatile("ldmatrix.sync.aligned.m8n8.x2.trans.shared.b16 {%0,%1},[%2];" \
                 : "=r"(r0), "=r"(r1) : "r"(ad))

__device__ __forceinline__ void cp16(uint32_t dst, const void* src) {
    asm volatile("cp.async.cg.shared.global [%0],[%1],16;" :: "r"(dst), "l"(src));
}
__device__ __forceinline__ void cpcommit() { asm volatile("cp.async.commit_group;"); }
__device__ __forceinline__ void cpwait2()  { asm volatile("cp.async.wait_group 2;"); }

__device__ __forceinline__ void split2h(float x, float y, uint32_t& hi, uint32_t& lo) {
    __half2 h = __floats2half2_rn(x, y);
    hi = *reinterpret_cast<uint32_t*>(&h);
    float rx = x - __low2float(h);
    float ry = y - __high2float(h);
    __half2 l = __floats2half2_rn(rx, ry);
    lo = *reinterpret_cast<uint32_t*>(&l);
}
__device__ __forceinline__ uint32_t pack2h(float x, float y) {
    __half2 h = __floats2half2_rn(x, y);
    return *reinterpret_cast<uint32_t*>(&h);
}
__device__ __forceinline__ uint32_t ex2h2(uint32_t a) {
    uint32_t d;
    asm("ex2.approx.f16x2 %0, %1;" : "=r"(d) : "r"(a));
    return d;
}

#define L2E 1.44269504f

// ============================================================
// Kernel 1a: q' = L2E * Wk^T q  (bias cancels; scores in log2 units)
// ============================================================
__global__ void __launch_bounds__(128)
qprime_kernel(const float* __restrict__ query, const float* __restrict__ Wk) {
    __shared__ float sW[D66 * D66];
    const int tid = threadIdx.x;
    const int row = blockIdx.x * 128 + tid;
    for (int i = tid; i < D66 * D66; i += 128) sW[i] = Wk[i];
    __syncthreads();

    float qr[D66];
    const float2* qp = (const float2*)(query + (size_t)row * D66);
    #pragma unroll
    for (int c = 0; c < 33; c++) { float2 v = qp[c]; qr[2*c] = v.x; qr[2*c+1] = v.y; }

    __half* Qh = g_qp;
    __half* Ql = g_qp + (size_t)NQT * DP;
    const size_t rb = (size_t)row * DP;

    #pragma unroll 1
    for (int j = 0; j < D66; j += 2) {
        float a0 = 0.0f, a1 = 0.0f;
        #pragma unroll
        for (int d = 0; d < D66; d++) {
            a0 = fmaf(qr[d], sW[d * D66 + j], a0);
            a1 = fmaf(qr[d], sW[d * D66 + j + 1], a1);
        }
        uint32_t hi, lo;
        split2h(a0 * L2E, a1 * L2E, hi, lo);
        *(uint32_t*)(Qh + rb + j) = hi;
        *(uint32_t*)(Ql + rb + j) = lo;
    }
    #pragma unroll
    for (int c = 33; c < DP / 2; c++) {
        *(uint32_t*)(Qh + rb + 2 * c) = 0u;
        *(uint32_t*)(Ql + rb + 2 * c) = 0u;
    }
}

// ============================================================
// Kernel 1b: x -> fp16, padded to DP=72
// ============================================================
__global__ void __launch_bounds__(256)
xsplit_kernel(const float* __restrict__ x) {
    const int n = blockIdx.x * 256 + threadIdx.x;
    const size_t rb = (size_t)n * DP;
    const float2* xp = (const float2*)(x + (size_t)n * D66);
    #pragma unroll
    for (int c = 0; c < 33; c++) {
        float2 v = xp[c];
        *(uint32_t*)(g_xh + rb + 2 * c) = pack2h(v.x, v.y);
    }
    #pragma unroll
    for (int c = 33; c < DP / 2; c++)
        *(uint32_t*)(g_xh + rb + 2 * c) = 0u;
}

// ============================================================
// Kernel 2: flash — lagged max with exact fallback:
//   fast path (ballot says all s <= m+11): exp with stale m, no shuffles
//   slow path (rare / first chunk): exact reduce + rescale before exp
//   post-PV: reduce chunk max, ratchet m, rescale o,l (exact algebra)
// exp interleaved with PV at kc2 granularity (asm order = issue order).
// ============================================================
extern __shared__ __half smbuf[];

__global__ void __launch_bounds__(128, 2)
flash_kernel() {
    const int tid  = threadIdx.x;
    const int lane = tid & 31;
    const int w    = tid >> 5;
    const int qtile = blockIdx.x % 64;
    const int split = blockIdx.x / 64;          // 0..8
    const int q0w = qtile * 128 + w * 32;
    const int chLo = (split * NCHALL) / SPLITS;
    const int chHi = ((split + 1) * NCHALL) / SPLITS;

    const int g  = lane >> 2;
    const int t  = lane & 3;
    const int q8 = lane >> 3;
    const int r  = lane & 7;

    const uint32_t sbase = (uint32_t)__cvta_generic_to_shared(smbuf);

    // ---- q' fragments (resident, hi/lo; k8 tail hi only) ----
    uint32_t aqh[2][4][4], aql[2][4][4], aq8h[2][2];
    {
        const __half* Qh = g_qp;
        const __half* Ql = g_qp + (size_t)NQT * DP;
        #pragma unroll
        for (int mt = 0; mt < 2; mt++) {
            const size_t r0 = (size_t)(q0w + 16 * mt + g) * DP;
            const size_t r1 = (size_t)(q0w + 16 * mt + g + 8) * DP;
            #pragma unroll
            for (int kc = 0; kc < 4; kc++) {
                int c0 = 16 * kc + 2 * t;
                aqh[mt][kc][0] = *(const uint32_t*)(Qh + r0 + c0);
                aqh[mt][kc][1] = *(const uint32_t*)(Qh + r1 + c0);
                aqh[mt][kc][2] = *(const uint32_t*)(Qh + r0 + c0 + 8);
                aqh[mt][kc][3] = *(const uint32_t*)(Qh + r1 + c0 + 8);
                aql[mt][kc][0] = *(const uint32_t*)(Ql + r0 + c0);
                aql[mt][kc][1] = *(const uint32_t*)(Ql + r1 + c0);
                aql[mt][kc][2] = *(const uint32_t*)(Ql + r0 + c0 + 8);
                aql[mt][kc][3] = *(const uint32_t*)(Ql + r1 + c0 + 8);
            }
            int c8 = 64 + 2 * t;
            aq8h[mt][0] = *(const uint32_t*)(Qh + r0 + c8);
            aq8h[mt][1] = *(const uint32_t*)(Qh + r1 + c8);
        }
    }

    const uint32_t qk_off  = ((8 * (q8 >> 1) + r) * SKW + 8 * (q8 & 1)) * 2;
    const uint32_t qk8_off = ((8 * (q8 & 1) + r) * SKW + 64) * 2;
    const uint32_t pv_off  = ((8 * (q8 & 1) + r) * SKW + 8 * (q8 >> 1)) * 2;
    const uint32_t pv2_off = ((8 * (q8 & 1) + r) * SKW + 64) * 2;

    float o[2][9][4];
    #pragma unroll
    for (int mt = 0; mt < 2; mt++)
        #pragma unroll
        for (int i = 0; i < 9; i++)
            #pragma unroll
            for (int c = 0; c < 4; c++) o[mt][i][c] = 0.0f;
    float m[4] = {-1e30f, -1e30f, -1e30f, -1e30f};   // running max (log2)
    float l[4] = {0.0f, 0.0f, 0.0f, 0.0f};

    #define PREFETCH(CH)                                                          \
    do {                                                                          \
        const size_t kb = (size_t)(CH) * CK;                                      \
        const uint32_t bb = sbase + ((CH) & (NBUF - 1)) * ABYTES;                 \
        _Pragma("unroll")                                                         \
        for (int jj = 0; jj < 5; jj++) {                                          \
            int j = tid + jj * 128;                                               \
            if (j < NGROUPS) {                                                    \
                int row = j / 9;                                                  \
                int cc  = j - row * 9;                                            \
                const __half* src = g_xh + (kb + row) * DP + cc * 8;              \
                uint32_t dst = bb + (row * SKW + cc * 8) * 2;                     \
                cp16(dst, src);                                                   \
            }                                                                     \
        }                                                                         \
    } while (0)

    PREFETCH(chLo); cpcommit();
    if (chLo + 1 < chHi) PREFETCH(chLo + 1);
    cpcommit();

    for (int ch = chLo; ch < chHi; ch++) {
        if (ch + 2 < chHi) PREFETCH(ch + 2);
        cpcommit();
        cpwait2();
        __syncthreads();

        const uint32_t sX = sbase + (ch & (NBUF - 1)) * ABYTES;

        // ---- QK: S(log2) = (q'h + q'l) . X ----
        float s[2][8][4];
        #pragma unroll
        for (int mt = 0; mt < 2; mt++)
            #pragma unroll
            for (int i = 0; i < 8; i++)
                #pragma unroll
                for (int c = 0; c < 4; c++) s[mt][i][c] = 0.0f;

        #pragma unroll
        for (int kc = 0; kc < 4; kc++) {
            #pragma unroll
            for (int jn2 = 0; jn2 < 4; jn2++) {
                uint32_t off = (16 * jn2 * SKW + 16 * kc) * 2 + qk_off;
                uint32_t b0, b1, b2, b3;
                LDSM4(b0, b1, b2, b3, sX + off);
                #pragma unroll
                for (int mt = 0; mt < 2; mt++) {
                    MMA16(s[mt][2 * jn2],     aqh[mt][kc], b0, b1);
                    MMA16(s[mt][2 * jn2],     aql[mt][kc], b0, b1);
                    MMA16(s[mt][2 * jn2 + 1], aqh[mt][kc], b2, b3);
                    MMA16(s[mt][2 * jn2 + 1], aql[mt][kc], b2, b3);
                }
            }
        }
        #pragma unroll
        for (int jn2 = 0; jn2 < 4; jn2++) {
            uint32_t off = (16 * jn2 * SKW) * 2 + qk8_off;
            uint32_t b0, b1;
            LDSM2(b0, b1, sX + off);
            #pragma unroll
            for (int mt = 0; mt < 2; mt++) {
                MMA8(s[mt][2 * jn2],     aq8h[mt][0], aq8h[mt][1], b0);
                MMA8(s[mt][2 * jn2 + 1], aq8h[mt][0], aq8h[mt][1], b1);
            }
        }

        // ---- per-thread chunk max (FMA pipe) ----
        float t0 = -1e30f, t1 = -1e30f, t2 = -1e30f, t3 = -1e30f;
        #pragma unroll
        for (int i = 0; i < 8; i++) {
            t0 = fmaxf(t0, fmaxf(s[0][i][0], s[0][i][1]));
            t1 = fmaxf(t1, fmaxf(s[0][i][2], s[0][i][3]));
            t2 = fmaxf(t2, fmaxf(s[1][i][0], s[1][i][1]));
            t3 = fmaxf(t3, fmaxf(s[1][i][2], s[1][i][3]));
        }

        // ---- ballot: is the stale max safe? (guarantees p <= 2^11) ----
        bool redone = false;
        {
            bool risky = (t0 > m[0] + JMP) | (t1 > m[1] + JMP) |
                         (t2 > m[2] + JMP) | (t3 > m[3] + JMP);
            if (__any_sync(0xffffffffu, risky)) {
                // slow path: exact reduce + rescale BEFORE exp (R11 behavior)
                t0 = fmaxf(t0, __shfl_xor_sync(0xffffffffu, t0, 1));
                t1 = fmaxf(t1, __shfl_xor_sync(0xffffffffu, t1, 1));
                t2 = fmaxf(t2, __shfl_xor_sync(0xffffffffu, t2, 1));
                t3 = fmaxf(t3, __shfl_xor_sync(0xffffffffu, t3, 1));
                t0 = fmaxf(t0, __shfl_xor_sync(0xffffffffu, t0, 2));
                t1 = fmaxf(t1, __shfl_xor_sync(0xffffffffu, t1, 2));
                t2 = fmaxf(t2, __shfl_xor_sync(0xffffffffu, t2, 2));
                t3 = fmaxf(t3, __shfl_xor_sync(0xffffffffu, t3, 2));
                float mN0 = fmaxf(m[0], t0), mN1 = fmaxf(m[1], t1);
                float mN2 = fmaxf(m[2], t2), mN3 = fmaxf(m[3], t3);
                float a0 = exp2f(m[0] - mN0);
                float a1 = exp2f(m[1] - mN1);
                float a2 = exp2f(m[2] - mN2);
                float a3 = exp2f(m[3] - mN3);
                l[0] *= a0; l[1] *= a1; l[2] *= a2; l[3] *= a3;
                #pragma unroll
                for (int i = 0; i < 9; i++) {
                    o[0][i][0] *= a0; o[0][i][1] *= a0;
                    o[0][i][2] *= a1; o[0][i][3] *= a1;
                    o[1][i][0] *= a2; o[1][i][1] *= a2;
                    o[1][i][2] *= a3; o[1][i][3] *= a3;
                }
                m[0] = mN0; m[1] = mN1; m[2] = mN2; m[3] = mN3;
                redone = true;
            }
        }

        // ---- exp + PV interleaved per kc2 slice ----
        uint32_t ph[2][4][4];
        #pragma unroll
        for (int u = 0; u < 4; u++) {
            #pragma unroll
            for (int mt = 0; mt < 2; mt++) {
                const float n0 = m[2 * mt];
                const float n1 = m[2 * mt + 1];
                ph[mt][u][0] = ex2h2(pack2h(s[mt][2*u][0]   - n0, s[mt][2*u][1]   - n0));
                ph[mt][u][1] = ex2h2(pack2h(s[mt][2*u][2]   - n1, s[mt][2*u][3]   - n1));
                ph[mt][u][2] = ex2h2(pack2h(s[mt][2*u+1][0] - n0, s[mt][2*u+1][1] - n0));
                ph[mt][u][3] = ex2h2(pack2h(s[mt][2*u+1][2] - n1, s[mt][2*u+1][3] - n1));
            }
            #pragma unroll
            for (int dn2 = 0; dn2 < 4; dn2++) {
                uint32_t off = (16 * u * SKW + 16 * dn2) * 2 + pv_off;
                uint32_t b0, b1, b2, b3;
                LDSM4T(b0, b1, b2, b3, sX + off);
                #pragma unroll
                for (int mt = 0; mt < 2; mt++) {
                    MMA16(o[mt][2 * dn2],     ph[mt][u], b0, b1);
                    MMA16(o[mt][2 * dn2 + 1], ph[mt][u], b2, b3);
                }
            }
            {
                uint32_t off = (16 * u * SKW) * 2 + pv2_off;
                uint32_t b0, b1;
                LDSM2T(b0, b1, sX + off);
                #pragma unroll
                for (int mt = 0; mt < 2; mt++)
                    MMA16(o[mt][8], ph[mt][u], b0, b1);
            }
        }

        // ---- l accumulation (half2; bounded by 8*2^11 = 2^14 < fp16 max) ----
        #pragma unroll
        for (int mt = 0; mt < 2; mt++) {
            __half2 lA2 = __floats2half2_rn(0.f, 0.f);
            __half2 lB2 = __floats2half2_rn(0.f, 0.f);
            #pragma unroll
            for (int u = 0; u < 4; u++) {
                lA2 = __hadd2(lA2, *reinterpret_cast<__half2*>(&ph[mt][u][0]));
                lA2 = __hadd2(lA2, *reinterpret_cast<__half2*>(&ph[mt][u][2]));
                lB2 = __hadd2(lB2, *reinterpret_cast<__half2*>(&ph[mt][u][1]));
                lB2 = __hadd2(lB2, *reinterpret_cast<__half2*>(&ph[mt][u][3]));
            }
            float2 va = __half22float2(lA2);
            float2 vb = __half22float2(lB2);
            l[2 * mt]     += va.x + va.y;
            l[2 * mt + 1] += vb.x + vb.y;
        }

        // ---- post-PV: ratchet max, rescale o,l (off critical path) ----
        if (!redone) {
            t0 = fmaxf(t0, __shfl_xor_sync(0xffffffffu, t0, 1));
            t1 = fmaxf(t1, __shfl_xor_sync(0xffffffffu, t1, 1));
            t2 = fmaxf(t2, __shfl_xor_sync(0xffffffffu, t2, 1));
            t3 = fmaxf(t3, __shfl_xor_sync(0xffffffffu, t3, 1));
            t0 = fmaxf(t0, __shfl_xor_sync(0xffffffffu, t0, 2));
            t1 = fmaxf(t1, __shfl_xor_sync(0xffffffffu, t1, 2));
            t2 = fmaxf(t2, __shfl_xor_sync(0xffffffffu, t2, 2));
            t3 = fmaxf(t3, __shfl_xor_sync(0xffffffffu, t3, 2));
            float mN0 = fmaxf(m[0], t0), mN1 = fmaxf(m[1], t1);
            float mN2 = fmaxf(m[2], t2), mN3 = fmaxf(m[3], t3);
            bool nochg = (mN0 == m[0]) & (mN1 == m[1]) &
                         (mN2 == m[2]) & (mN3 == m[3]);
            if (!__all_sync(0xffffffffu, nochg)) {
                float a0 = exp2f(m[0] - mN0);
                float a1 = exp2f(m[1] - mN1);
                float a2 = exp2f(m[2] - mN2);
                float a3 = exp2f(m[3] - mN3);
                l[0] *= a0; l[1] *= a1; l[2] *= a2; l[3] *= a3;
                #pragma unroll
                for (int i = 0; i < 9; i++) {
                    o[0][i][0] *= a0; o[0][i][1] *= a0;
                    o[0][i][2] *= a1; o[0][i][3] *= a1;
                    o[1][i][0] *= a2; o[1][i][1] *= a2;
                    o[1][i][2] *= a3; o[1][i][3] *= a3;
                }
                m[0] = mN0; m[1] = mN1; m[2] = mN2; m[3] = mN3;
            }
        }
        // no trailing sync: ring-of-4 + distance-2 prefetch keeps the live
        // buffer safe (all warps passed this iteration's barrier).
    }

    // ---- epilogue ----
    #pragma unroll
    for (int i = 0; i < 4; i++) {
        l[i] += __shfl_xor_sync(0xffffffffu, l[i], 1);
        l[i] += __shfl_xor_sync(0xffffffffu, l[i], 2);
    }
    if ((lane & 3) == 0) {
        #pragma unroll
        for (int mt = 0; mt < 2; mt++) {
            g_ml[split * NQT + q0w + 16 * mt + g]     = make_float2(m[2*mt],   l[2*mt]);
            g_ml[split * NQT + q0w + 16 * mt + g + 8] = make_float2(m[2*mt+1], l[2*mt+1]);
        }
    }
    const size_t ob = (size_t)split * NQT;
    #pragma unroll
    for (int mt = 0; mt < 2; mt++) {
        #pragma unroll
        for (int dn = 0; dn < 9; dn++) {
            int d0 = 8 * dn + 2 * t;
            if (d0 < D66) {
                *(float2*)(g_part + (ob + q0w + 16*mt + g)     * D66 + d0) =
                    make_float2(o[mt][dn][0], o[mt][dn][1]);
                *(float2*)(g_part + (ob + q0w + 16*mt + g + 8) * D66 + d0) =
                    make_float2(o[mt][dn][2], o[mt][dn][3]);
            }
        }
    }
}

// ============================================================
// Kernel 3: combine — 8 threads/query, LSE merge over 9 (log2 units)
// ============================================================
__global__ void __launch_bounds__(256)
combine_kernel(float* __restrict__ out) {
    const int tid = threadIdx.x;
    const int part = tid & 7;
    const int q = blockIdx.x * 32 + (tid >> 3);

    float M = -1e30f;
    float mx[SPLITS], lx[SPLITS];
    #pragma unroll
    for (int s = 0; s < SPLITS; s++) {
        float2 v = g_ml[s * NQT + q];
        mx[s] = v.x; lx[s] = v.y;
        M = fmaxf(M, v.x);
    }
    float wgt[SPLITS];
    float l = 0.0f;
    #pragma unroll
    for (int s = 0; s < SPLITS; s++) {
        wgt[s] = exp2f(mx[s] - M);
        l += wgt[s] * lx[s];
    }
    float inv = 1.0f / l;

    #pragma unroll
    for (int i = 0; i < 5; i++) {
        int pr = part * 5 + i;          // d-pair index, 0..39
        if (pr < 33) {
            float ax = 0.0f, ay = 0.0f;
            #pragma unroll
            for (int s = 0; s < SPLITS; s++) {
                float2 v = *(const float2*)(g_part + ((size_t)s * NQT + q) * D66 + 2 * pr);
                ax = fmaf(wgt[s], v.x, ax);
                ay = fmaf(wgt[s], v.y, ay);
            }
            out[(size_t)q * D66 + 2 * pr]     = ax * inv;
            out[(size_t)q * D66 + 2 * pr + 1] = ay * inv;
        }
    }
}

// ============================================================
extern "C" void kernel_launch(void* const* d_in, const int* in_sizes, int n_in,
                              void* d_out, int out_size) {
    const float* x     = (const float*)d_in[0];
    const float* query = (const float*)d_in[1];
    const float* Wk    = (const float*)d_in[2];
    // bk unused: q.b cancels in softmax
    float* out = (float*)d_out;

    const int smem_bytes = NBUF * ABYTES;   // 36864
    cudaFuncSetAttribute(flash_kernel,
                         cudaFuncAttributeMaxDynamicSharedMemorySize, smem_bytes);

    qprime_kernel<<<NQT / 128, 128>>>(query, Wk);
    xsplit_kernel<<<NK / 256, 256>>>(x);
    flash_kernel<<<64 * SPLITS, 128, smem_bytes>>>();
    combine_kernel<<<NQT / 32, 256>>>(out);
}

// round 14
// speedup vs baseline: 1.2858x; 1.2858x over previous
#include <cuda_runtime.h>
#include <cuda_fp16.h>
#include <cstdint>

#define D66     66
#define DP      72                 // padded dim (4x k16 + 1x k8)
#define NK      65536
#define NQT     8192
#define SPLITS  9
#define NCHALL  (NK / 64)          // 1024 total chunks
#define CK      64
#define SKW     72                 // smem row pitch (fp16); 144B rows
#define ABYTES  (CK * SKW * 2)     // 9216 = one chunk buffer
#define NBUF    4
#define NGROUPS (CK * 9)           // 576 16B-groups per chunk

// static device scratch (no cudaMalloc)
__device__ __align__(16) __half g_xh[(size_t)NK * DP];        // fp16(x)
__device__ __align__(16) __half g_qp[(size_t)NQT * DP];       // fp16(L2E*q')
__device__ float  g_part[(size_t)SPLITS * NQT * D66];
__device__ float2 g_ml[SPLITS * NQT];

// ---------------- asm helpers ----------------
#define MMA16(dv, av, b0_, b1_)                                             \
    asm volatile("mma.sync.aligned.m16n8k16.row.col.f32.f16.f16.f32 "       \
                 "{%0,%1,%2,%3},{%4,%5,%6,%7},{%8,%9},{%0,%1,%2,%3};"       \
                 : "+f"(dv[0]), "+f"(dv[1]), "+f"(dv[2]), "+f"(dv[3])       \
                 : "r"(av[0]), "r"(av[1]), "r"(av[2]), "r"(av[3]),          \
                   "r"(b0_), "r"(b1_))

#define MMA8(dv, a0_, a1_, b0_)                                             \
    asm volatile("mma.sync.aligned.m16n8k8.row.col.f32.f16.f16.f32 "        \
                 "{%0,%1,%2,%3},{%4,%5},{%6},{%0,%1,%2,%3};"                \
                 : "+f"(dv[0]), "+f"(dv[1]), "+f"(dv[2]), "+f"(dv[3])       \
                 : "r"(a0_), "r"(a1_), "r"(b0_))

#define LDSM4(r0, r1, r2, r3, ad)                                           \
    asm volatile("ldmatrix.sync.aligned.m8n8.x4.shared.b16 {%0,%1,%2,%3},[%4];" \
                 : "=r"(r0), "=r"(r1), "=r"(r2), "=r"(r3) : "r"(ad))

#define LDSM2(r0, r1, ad)                                                   \
    asm volatile("ldmatrix.sync.aligned.m8n8.x2.shared.b16 {%0,%1},[%2];"   \
                 : "=r"(r0), "=r"(r1) : "r"(ad))

#define LDSM4T(r0, r1, r2, r3, ad)                                          \
    asm volatile("ldmatrix.sync.aligned.m8n8.x4.trans.shared.b16 {%0,%1,%2,%3},[%4];" \
                 : "=r"(r0), "=r"(r1), "=r"(r2), "=r"(r3) : "r"(ad))

#define LDSM2T(r0, r1, ad)                                                  \
    asm volatile("ldmatrix.sync.aligned.m8n8.x2.trans.shared.b16 {%0,%1},[%2];" \
                 : "=r"(r0), "=r"(r1) : "r"(ad))

__device__ __forceinline__ void cp16(uint32_t dst, const void* src) {
    asm volatile("cp.async.cg.shared.global [%0],[%1],16;" :: "r"(dst), "l"(src));
}
__device__ __forceinline__ void cpcommit() { asm volatile("cp.async.commit_group;"); }
__device__ __forceinline__ void cpwait2()  { asm volatile("cp.async.wait_group 2;"); }

__device__ __forceinline__ uint32_t pack2h(float x, float y) {
    __half2 h = __floats2half2_rn(x, y);
    return *reinterpret_cast<uint32_t*>(&h);
}
__device__ __forceinline__ uint32_t ex2h2(uint32_t a) {
    uint32_t d;
    asm("ex2.approx.f16x2 %0, %1;" : "=r"(d) : "r"(a));
    return d;
}

#define L2E 1.44269504f

// ============================================================
// Kernel 1a: q' = fp16(L2E * Wk^T q)  (bias cancels; log2 units)
// ============================================================
__global__ void __launch_bounds__(128)
qprime_kernel(const float* __restrict__ query, const float* __restrict__ Wk) {
    __shared__ float sW[D66 * D66];
    const int tid = threadIdx.x;
    const int row = blockIdx.x * 128 + tid;
    for (int i = tid; i < D66 * D66; i += 128) sW[i] = Wk[i];
    __syncthreads();

    float qr[D66];
    const float2* qp = (const float2*)(query + (size_t)row * D66);
    #pragma unroll
    for (int c = 0; c < 33; c++) { float2 v = qp[c]; qr[2*c] = v.x; qr[2*c+1] = v.y; }

    const size_t rb = (size_t)row * DP;

    #pragma unroll 1
    for (int j = 0; j < D66; j += 2) {
        float a0 = 0.0f, a1 = 0.0f;
        #pragma unroll
        for (int d = 0; d < D66; d++) {
            a0 = fmaf(qr[d], sW[d * D66 + j], a0);
            a1 = fmaf(qr[d], sW[d * D66 + j + 1], a1);
        }
        *(uint32_t*)(g_qp + rb + j) = pack2h(a0 * L2E, a1 * L2E);
    }
    #pragma unroll
    for (int c = 33; c < DP / 2; c++)
        *(uint32_t*)(g_qp + rb + 2 * c) = 0u;
}

// ============================================================
// Kernel 1b: x -> fp16, padded to DP=72
// ============================================================
__global__ void __launch_bounds__(256)
xsplit_kernel(const float* __restrict__ x) {
    const int n = blockIdx.x * 256 + threadIdx.x;
    const size_t rb = (size_t)n * DP;
    const float2* xp = (const float2*)(x + (size_t)n * D66);
    #pragma unroll
    for (int c = 0; c < 33; c++) {
        float2 v = xp[c];
        *(uint32_t*)(g_xh + rb + 2 * c) = pack2h(v.x, v.y);
    }
    #pragma unroll
    for (int c = 33; c < DP / 2; c++)
        *(uint32_t*)(g_xh + rb + 2 * c) = 0u;
}

// ============================================================
// Kernel 2: flash — 4 warps x 32 q-rows, 1-pass QK, 1-pass PV,
// exact online max, 4-buffer ring, 1 sync/chunk
// ============================================================
extern __shared__ __half smbuf[];

__global__ void __launch_bounds__(128, 2)
flash_kernel() {
    const int tid  = threadIdx.x;
    const int lane = tid & 31;
    const int w    = tid >> 5;
    const int qtile = blockIdx.x % 64;
    const int split = blockIdx.x / 64;          // 0..8
    const int q0w = qtile * 128 + w * 32;
    const int chLo = (split * NCHALL) / SPLITS;
    const int chHi = ((split + 1) * NCHALL) / SPLITS;

    const int g  = lane >> 2;
    const int t  = lane & 3;
    const int q8 = lane >> 3;
    const int r  = lane & 7;

    const uint32_t sbase = (uint32_t)__cvta_generic_to_shared(smbuf);

    // ---- q' fragments (resident; single fp16 copy) ----
    uint32_t aq[2][4][4], aq8[2][2];
    {
        #pragma unroll
        for (int mt = 0; mt < 2; mt++) {
            const size_t r0 = (size_t)(q0w + 16 * mt + g) * DP;
            const size_t r1 = (size_t)(q0w + 16 * mt + g + 8) * DP;
            #pragma unroll
            for (int kc = 0; kc < 4; kc++) {
                int c0 = 16 * kc + 2 * t;
                aq[mt][kc][0] = *(const uint32_t*)(g_qp + r0 + c0);
                aq[mt][kc][1] = *(const uint32_t*)(g_qp + r1 + c0);
                aq[mt][kc][2] = *(const uint32_t*)(g_qp + r0 + c0 + 8);
                aq[mt][kc][3] = *(const uint32_t*)(g_qp + r1 + c0 + 8);
            }
            int c8 = 64 + 2 * t;
            aq8[mt][0] = *(const uint32_t*)(g_qp + r0 + c8);
            aq8[mt][1] = *(const uint32_t*)(g_qp + r1 + c8);
        }
    }

    const uint32_t qk_off  = ((8 * (q8 >> 1) + r) * SKW + 8 * (q8 & 1)) * 2;
    const uint32_t qk8_off = ((8 * (q8 & 1) + r) * SKW + 64) * 2;
    const uint32_t pv_off  = ((8 * (q8 & 1) + r) * SKW + 8 * (q8 >> 1)) * 2;
    const uint32_t pv2_off = ((8 * (q8 & 1) + r) * SKW + 64) * 2;

    float o[2][9][4];
    #pragma unroll
    for (int mt = 0; mt < 2; mt++)
        #pragma unroll
        for (int i = 0; i < 9; i++)
            #pragma unroll
            for (int c = 0; c < 4; c++) o[mt][i][c] = 0.0f;
    float m[4] = {-1e30f, -1e30f, -1e30f, -1e30f};   // log2 units
    float l[4] = {0.0f, 0.0f, 0.0f, 0.0f};

    #define PREFETCH(CH)                                                          \
    do {                                                                          \
        const size_t kb = (size_t)(CH) * CK;                                      \
        const uint32_t bb = sbase + ((CH) & (NBUF - 1)) * ABYTES;                 \
        _Pragma("unroll")                                                         \
        for (int jj = 0; jj < 5; jj++) {                                          \
            int j = tid + jj * 128;                                               \
            if (j < NGROUPS) {                                                    \
                int row = j / 9;                                                  \
                int cc  = j - row * 9;                                            \
                const __half* src = g_xh + (kb + row) * DP + cc * 8;              \
                uint32_t dst = bb + (row * SKW + cc * 8) * 2;                     \
                cp16(dst, src);                                                   \
            }                                                                     \
        }                                                                         \
    } while (0)

    PREFETCH(chLo); cpcommit();
    if (chLo + 1 < chHi) PREFETCH(chLo + 1);
    cpcommit();

    for (int ch = chLo; ch < chHi; ch++) {
        if (ch + 2 < chHi) PREFETCH(ch + 2);
        cpcommit();
        cpwait2();
        __syncthreads();

        const uint32_t sX = sbase + (ch & (NBUF - 1)) * ABYTES;

        // ---- QK: S(log2) = q' . X  (single pass) ----
        float s[2][8][4];
        #pragma unroll
        for (int mt = 0; mt < 2; mt++)
            #pragma unroll
            for (int i = 0; i < 8; i++)
                #pragma unroll
                for (int c = 0; c < 4; c++) s[mt][i][c] = 0.0f;

        #pragma unroll
        for (int kc = 0; kc < 4; kc++) {
            #pragma unroll
            for (int jn2 = 0; jn2 < 4; jn2++) {
                uint32_t off = (16 * jn2 * SKW + 16 * kc) * 2 + qk_off;
                uint32_t b0, b1, b2, b3;
                LDSM4(b0, b1, b2, b3, sX + off);
                #pragma unroll
                for (int mt = 0; mt < 2; mt++) {
                    MMA16(s[mt][2 * jn2],     aq[mt][kc], b0, b1);
                    MMA16(s[mt][2 * jn2 + 1], aq[mt][kc], b2, b3);
                }
            }
        }
        #pragma unroll
        for (int jn2 = 0; jn2 < 4; jn2++) {
            uint32_t off = (16 * jn2 * SKW) * 2 + qk8_off;
            uint32_t b0, b1;
            LDSM2(b0, b1, sX + off);
            #pragma unroll
            for (int mt = 0; mt < 2; mt++) {
                MMA8(s[mt][2 * jn2],     aq8[mt][0], aq8[mt][1], b0);
                MMA8(s[mt][2 * jn2 + 1], aq8[mt][0], aq8[mt][1], b1);
            }
        }

        // ---- online softmax (exact): reduce, rescale-if-needed, exp ----
        uint32_t ph[2][4][4];
        float mN[4];
        {
            float mx0 = -1e30f, mx1 = -1e30f, mx2 = -1e30f, mx3 = -1e30f;
            #pragma unroll
            for (int i = 0; i < 8; i++) {
                mx0 = fmaxf(mx0, fmaxf(s[0][i][0], s[0][i][1]));
                mx1 = fmaxf(mx1, fmaxf(s[0][i][2], s[0][i][3]));
                mx2 = fmaxf(mx2, fmaxf(s[1][i][0], s[1][i][1]));
                mx3 = fmaxf(mx3, fmaxf(s[1][i][2], s[1][i][3]));
            }
            mx0 = fmaxf(mx0, __shfl_xor_sync(0xffffffffu, mx0, 1));
            mx1 = fmaxf(mx1, __shfl_xor_sync(0xffffffffu, mx1, 1));
            mx2 = fmaxf(mx2, __shfl_xor_sync(0xffffffffu, mx2, 1));
            mx3 = fmaxf(mx3, __shfl_xor_sync(0xffffffffu, mx3, 1));
            mx0 = fmaxf(mx0, __shfl_xor_sync(0xffffffffu, mx0, 2));
            mx1 = fmaxf(mx1, __shfl_xor_sync(0xffffffffu, mx1, 2));
            mx2 = fmaxf(mx2, __shfl_xor_sync(0xffffffffu, mx2, 2));
            mx3 = fmaxf(mx3, __shfl_xor_sync(0xffffffffu, mx3, 2));
            mN[0] = fmaxf(m[0], mx0);
            mN[1] = fmaxf(m[1], mx1);
            mN[2] = fmaxf(m[2], mx2);
            mN[3] = fmaxf(m[3], mx3);
            bool nochg = (mN[0] == m[0]) & (mN[1] == m[1]) &
                         (mN[2] == m[2]) & (mN[3] == m[3]);
            if (!__all_sync(0xffffffffu, nochg)) {
                float a0 = exp2f(m[0] - mN[0]);
                float a1 = exp2f(m[1] - mN[1]);
                float a2 = exp2f(m[2] - mN[2]);
                float a3 = exp2f(m[3] - mN[3]);
                l[0] *= a0; l[1] *= a1; l[2] *= a2; l[3] *= a3;
                #pragma unroll
                for (int i = 0; i < 9; i++) {
                    o[0][i][0] *= a0; o[0][i][1] *= a0;
                    o[0][i][2] *= a1; o[0][i][3] *= a1;
                    o[1][i][0] *= a2; o[1][i][1] *= a2;
                    o[1][i][2] *= a3; o[1][i][3] *= a3;
                }
                m[0] = mN[0]; m[1] = mN[1]; m[2] = mN[2]; m[3] = mN[3];
            }
        }
        #pragma unroll
        for (int mt = 0; mt < 2; mt++) {
            const float n0 = mN[2 * mt];
            const float n1 = mN[2 * mt + 1];
            __half2 lA2 = __floats2half2_rn(0.f, 0.f);
            __half2 lB2 = __floats2half2_rn(0.f, 0.f);
            #pragma unroll
            for (int u = 0; u < 4; u++) {
                ph[mt][u][0] = ex2h2(pack2h(s[mt][2*u][0]   - n0, s[mt][2*u][1]   - n0));
                ph[mt][u][1] = ex2h2(pack2h(s[mt][2*u][2]   - n1, s[mt][2*u][3]   - n1));
                ph[mt][u][2] = ex2h2(pack2h(s[mt][2*u+1][0] - n0, s[mt][2*u+1][1] - n0));
                ph[mt][u][3] = ex2h2(pack2h(s[mt][2*u+1][2] - n1, s[mt][2*u+1][3] - n1));
                lA2 = __hadd2(lA2, *reinterpret_cast<__half2*>(&ph[mt][u][0]));
                lA2 = __hadd2(lA2, *reinterpret_cast<__half2*>(&ph[mt][u][2]));
                lB2 = __hadd2(lB2, *reinterpret_cast<__half2*>(&ph[mt][u][1]));
                lB2 = __hadd2(lB2, *reinterpret_cast<__half2*>(&ph[mt][u][3]));
            }
            float2 va = __half22float2(lA2);
            float2 vb = __half22float2(lB2);
            l[2 * mt]     += va.x + va.y;
            l[2 * mt + 1] += vb.x + vb.y;
        }

        // ---- PV: O += P . X ----
        #pragma unroll
        for (int kc2 = 0; kc2 < 4; kc2++) {
            #pragma unroll
            for (int dn2 = 0; dn2 < 4; dn2++) {
                uint32_t off = (16 * kc2 * SKW + 16 * dn2) * 2 + pv_off;
                uint32_t b0, b1, b2, b3;
                LDSM4T(b0, b1, b2, b3, sX + off);
                #pragma unroll
                for (int mt = 0; mt < 2; mt++) {
                    MMA16(o[mt][2 * dn2],     ph[mt][kc2], b0, b1);
                    MMA16(o[mt][2 * dn2 + 1], ph[mt][kc2], b2, b3);
                }
            }
            {
                uint32_t off = (16 * kc2 * SKW) * 2 + pv2_off;
                uint32_t b0, b1;
                LDSM2T(b0, b1, sX + off);
                #pragma unroll
                for (int mt = 0; mt < 2; mt++)
                    MMA16(o[mt][8], ph[mt][kc2], b0, b1);
            }
        }
        // no trailing sync: ring-of-4 + distance-2 prefetch keeps the live
        // buffer safe (all warps passed this iteration's barrier).
    }

    // ---- epilogue ----
    #pragma unroll
    for (int i = 0; i < 4; i++) {
        l[i] += __shfl_xor_sync(0xffffffffu, l[i], 1);
        l[i] += __shfl_xor_sync(0xffffffffu, l[i], 2);
    }
    if ((lane & 3) == 0) {
        #pragma unroll
        for (int mt = 0; mt < 2; mt++) {
            g_ml[split * NQT + q0w + 16 * mt + g]     = make_float2(m[2*mt],   l[2*mt]);
            g_ml[split * NQT + q0w + 16 * mt + g + 8] = make_float2(m[2*mt+1], l[2*mt+1]);
        }
    }
    const size_t ob = (size_t)split * NQT;
    #pragma unroll
    for (int mt = 0; mt < 2; mt++) {
        #pragma unroll
        for (int dn = 0; dn < 9; dn++) {
            int d0 = 8 * dn + 2 * t;
            if (d0 < D66) {
                *(float2*)(g_part + (ob + q0w + 16*mt + g)     * D66 + d0) =
                    make_float2(o[mt][dn][0], o[mt][dn][1]);
                *(float2*)(g_part + (ob + q0w + 16*mt + g + 8) * D66 + d0) =
                    make_float2(o[mt][dn][2], o[mt][dn][3]);
            }
        }
    }
}

// ============================================================
// Kernel 3: combine — 8 threads/query, LSE merge over 9 (log2 units)
// ============================================================
__global__ void __launch_bounds__(256)
combine_kernel(float* __restrict__ out) {
    const int tid = threadIdx.x;
    const int part = tid & 7;
    const int q = blockIdx.x * 32 + (tid >> 3);

    float M = -1e30f;
    float mx[SPLITS], lx[SPLITS];
    #pragma unroll
    for (int s = 0; s < SPLITS; s++) {
        float2 v = g_ml[s * NQT + q];
        mx[s] = v.x; lx[s] = v.y;
        M = fmaxf(M, v.x);
    }
    float wgt[SPLITS];
    float l = 0.0f;
    #pragma unroll
    for (int s = 0; s < SPLITS; s++) {
        wgt[s] = exp2f(mx[s] - M);
        l += wgt[s] * lx[s];
    }
    float inv = 1.0f / l;

    #pragma unroll
    for (int i = 0; i < 5; i++) {
        int pr = part * 5 + i;          // d-pair index, 0..39
        if (pr < 33) {
            float ax = 0.0f, ay = 0.0f;
            #pragma unroll
            for (int s = 0; s < SPLITS; s++) {
                float2 v = *(const float2*)(g_part + ((size_t)s * NQT + q) * D66 + 2 * pr);
                ax = fmaf(wgt[s], v.x, ax);
                ay = fmaf(wgt[s], v.y, ay);
            }
            out[(size_t)q * D66 + 2 * pr]     = ax * inv;
            out[(size_t)q * D66 + 2 * pr + 1] = ay * inv;
        }
    }
}

// ============================================================
extern "C" void kernel_launch(void* const* d_in, const int* in_sizes, int n_in,
                              void* d_out, int out_size) {
    const float* x     = (const float*)d_in[0];
    const float* query = (const float*)d_in[1];
    const float* Wk    = (const float*)d_in[2];
    // bk unused: q.b cancels in softmax
    float* out = (float*)d_out;

    const int smem_bytes = NBUF * ABYTES;   // 36864
    cudaFuncSetAttribute(flash_kernel,
                         cudaFuncAttributeMaxDynamicSharedMemorySize, smem_bytes);

    qprime_kernel<<<NQT / 128, 128>>>(query, Wk);
    xsplit_kernel<<<NK / 256, 256>>>(x);
    flash_kernel<<<64 * SPLITS, 128, smem_bytes>>>();
    combine_kernel<<<NQT / 32, 256>>>(out);
}

// round 15
// speedup vs baseline: 1.2925x; 1.0052x over previous
#include <cuda_runtime.h>
#include <cuda_fp16.h>
#include <cstdint>

#define D66     66
#define DP      72                 // padded dim (4x k16 + 1x k8)
#define NK      65536
#define NQT     8192
#define SPLITS  9
#define NCHALL  (NK / 64)          // 1024 total chunks
#define CK      64
#define SKW     72                 // smem row pitch (fp16); 144B rows
#define ABYTES  (CK * SKW * 2)     // 9216 = one chunk buffer
#define NBUF    4
#define NGROUPS (CK * 9)           // 576 16B-groups per chunk

// static device scratch (no cudaMalloc)
__device__ __align__(16) __half g_xh[(size_t)NK * DP];        // fp16(x)
__device__ __align__(16) __half g_qp[(size_t)NQT * DP];       // fp16(L2E*q')
__device__ float  g_part[(size_t)SPLITS * NQT * D66];
__device__ float2 g_ml[SPLITS * NQT];

// ---------------- asm helpers ----------------
#define MMA16(dv, av, b0_, b1_)                                             \
    asm volatile("mma.sync.aligned.m16n8k16.row.col.f32.f16.f16.f32 "       \
                 "{%0,%1,%2,%3},{%4,%5,%6,%7},{%8,%9},{%0,%1,%2,%3};"       \
                 : "+f"(dv[0]), "+f"(dv[1]), "+f"(dv[2]), "+f"(dv[3])       \
                 : "r"(av[0]), "r"(av[1]), "r"(av[2]), "r"(av[3]),          \
                   "r"(b0_), "r"(b1_))

#define MMA8(dv, a0_, a1_, b0_)                                             \
    asm volatile("mma.sync.aligned.m16n8k8.row.col.f32.f16.f16.f32 "        \
                 "{%0,%1,%2,%3},{%4,%5},{%6},{%0,%1,%2,%3};"                \
                 : "+f"(dv[0]), "+f"(dv[1]), "+f"(dv[2]), "+f"(dv[3])       \
                 : "r"(a0_), "r"(a1_), "r"(b0_))

#define LDSM4(r0, r1, r2, r3, ad)                                           \
    asm volatile("ldmatrix.sync.aligned.m8n8.x4.shared.b16 {%0,%1,%2,%3},[%4];" \
                 : "=r"(r0), "=r"(r1), "=r"(r2), "=r"(r3) : "r"(ad))

#define LDSM2(r0, r1, ad)                                                   \
    asm volatile("ldmatrix.sync.aligned.m8n8.x2.shared.b16 {%0,%1},[%2];"   \
                 : "=r"(r0), "=r"(r1) : "r"(ad))

#define LDSM4T(r0, r1, r2, r3, ad)                                          \
    asm volatile("ldmatrix.sync.aligned.m8n8.x4.trans.shared.b16 {%0,%1,%2,%3},[%4];" \
                 : "=r"(r0), "=r"(r1), "=r"(r2), "=r"(r3) : "r"(ad))

#define LDSM2T(r0, r1, ad)                                                  \
    asm volatile("ldmatrix.sync.aligned.m8n8.x2.trans.shared.b16 {%0,%1},[%2];" \
                 : "=r"(r0), "=r"(r1) : "r"(ad))

__device__ __forceinline__ void cp16(uint32_t dst, const void* src) {
    asm volatile("cp.async.cg.shared.global [%0],[%1],16;" :: "r"(dst), "l"(src));
}
__device__ __forceinline__ void cpcommit() { asm volatile("cp.async.commit_group;"); }
__device__ __forceinline__ void cpwait2()  { asm volatile("cp.async.wait_group 2;"); }

__device__ __forceinline__ uint32_t pack2h(float x, float y) {
    __half2 h = __floats2half2_rn(x, y);
    return *reinterpret_cast<uint32_t*>(&h);
}
__device__ __forceinline__ uint32_t ex2h2(uint32_t a) {
    uint32_t d;
    asm("ex2.approx.f16x2 %0, %1;" : "=r"(d) : "r"(a));
    return d;
}
__device__ __forceinline__ __half2 h2(uint32_t a) {
    return *reinterpret_cast<__half2*>(&a);
}

#define L2E 1.44269504f

// ============================================================
// Kernel 1a: q' = fp16(L2E * Wk^T q)  (bias cancels; log2 units)
// ============================================================
__global__ void __launch_bounds__(128)
qprime_kernel(const float* __restrict__ query, const float* __restrict__ Wk) {
    __shared__ float sW[D66 * D66];
    const int tid = threadIdx.x;
    const int row = blockIdx.x * 128 + tid;
    for (int i = tid; i < D66 * D66; i += 128) sW[i] = Wk[i];
    __syncthreads();

    float qr[D66];
    const float2* qp = (const float2*)(query + (size_t)row * D66);
    #pragma unroll
    for (int c = 0; c < 33; c++) { float2 v = qp[c]; qr[2*c] = v.x; qr[2*c+1] = v.y; }

    const size_t rb = (size_t)row * DP;

    #pragma unroll 1
    for (int j = 0; j < D66; j += 2) {
        float a0 = 0.0f, a1 = 0.0f;
        #pragma unroll
        for (int d = 0; d < D66; d++) {
            a0 = fmaf(qr[d], sW[d * D66 + j], a0);
            a1 = fmaf(qr[d], sW[d * D66 + j + 1], a1);
        }
        *(uint32_t*)(g_qp + rb + j) = pack2h(a0 * L2E, a1 * L2E);
    }
    #pragma unroll
    for (int c = 33; c < DP / 2; c++)
        *(uint32_t*)(g_qp + rb + 2 * c) = 0u;
}

// ============================================================
// Kernel 1b: x -> fp16, padded to DP=72
// ============================================================
__global__ void __launch_bounds__(256)
xsplit_kernel(const float* __restrict__ x) {
    const int n = blockIdx.x * 256 + threadIdx.x;
    const size_t rb = (size_t)n * DP;
    const float2* xp = (const float2*)(x + (size_t)n * D66);
    #pragma unroll
    for (int c = 0; c < 33; c++) {
        float2 v = xp[c];
        *(uint32_t*)(g_xh + rb + 2 * c) = pack2h(v.x, v.y);
    }
    #pragma unroll
    for (int c = 33; c < DP / 2; c++)
        *(uint32_t*)(g_xh + rb + 2 * c) = 0u;
}

// ============================================================
// Kernel 2: flash — 1-pass QK, exact online max, PV software-
// pipelined per kc2 slice (exp -> MMA -> l-accum -> next LDSM),
// slice-0 B fragments preloaded under the max-reduce.
// ============================================================
extern __shared__ __half smbuf[];

__global__ void __launch_bounds__(128, 2)
flash_kernel() {
    const int tid  = threadIdx.x;
    const int lane = tid & 31;
    const int w    = tid >> 5;
    const int qtile = blockIdx.x % 64;
    const int split = blockIdx.x / 64;          // 0..8
    const int q0w = qtile * 128 + w * 32;
    const int chLo = (split * NCHALL) / SPLITS;
    const int chHi = ((split + 1) * NCHALL) / SPLITS;

    const int g  = lane >> 2;
    const int t  = lane & 3;
    const int q8 = lane >> 3;
    const int r  = lane & 7;

    const uint32_t sbase = (uint32_t)__cvta_generic_to_shared(smbuf);

    // ---- q' fragments (resident; single fp16 copy) ----
    uint32_t aq[2][4][4], aq8[2][2];
    {
        #pragma unroll
        for (int mt = 0; mt < 2; mt++) {
            const size_t r0 = (size_t)(q0w + 16 * mt + g) * DP;
            const size_t r1 = (size_t)(q0w + 16 * mt + g + 8) * DP;
            #pragma unroll
            for (int kc = 0; kc < 4; kc++) {
                int c0 = 16 * kc + 2 * t;
                aq[mt][kc][0] = *(const uint32_t*)(g_qp + r0 + c0);
                aq[mt][kc][1] = *(const uint32_t*)(g_qp + r1 + c0);
                aq[mt][kc][2] = *(const uint32_t*)(g_qp + r0 + c0 + 8);
                aq[mt][kc][3] = *(const uint32_t*)(g_qp + r1 + c0 + 8);
            }
            int c8 = 64 + 2 * t;
            aq8[mt][0] = *(const uint32_t*)(g_qp + r0 + c8);
            aq8[mt][1] = *(const uint32_t*)(g_qp + r1 + c8);
        }
    }

    const uint32_t qk_off  = ((8 * (q8 >> 1) + r) * SKW + 8 * (q8 & 1)) * 2;
    const uint32_t qk8_off = ((8 * (q8 & 1) + r) * SKW + 64) * 2;
    const uint32_t pv_off  = ((8 * (q8 & 1) + r) * SKW + 8 * (q8 >> 1)) * 2;
    const uint32_t pv2_off = ((8 * (q8 & 1) + r) * SKW + 64) * 2;

    float o[2][9][4];
    #pragma unroll
    for (int mt = 0; mt < 2; mt++)
        #pragma unroll
        for (int i = 0; i < 9; i++)
            #pragma unroll
            for (int c = 0; c < 4; c++) o[mt][i][c] = 0.0f;
    float m[4] = {-1e30f, -1e30f, -1e30f, -1e30f};   // log2 units
    float l[4] = {0.0f, 0.0f, 0.0f, 0.0f};

    #define PREFETCH(CH)                                                          \
    do {                                                                          \
        const size_t kb = (size_t)(CH) * CK;                                      \
        const uint32_t bb = sbase + ((CH) & (NBUF - 1)) * ABYTES;                 \
        _Pragma("unroll")                                                         \
        for (int jj = 0; jj < 5; jj++) {                                          \
            int j = tid + jj * 128;                                               \
            if (j < NGROUPS) {                                                    \
                int row = j / 9;                                                  \
                int cc  = j - row * 9;                                            \
                const __half* src = g_xh + (kb + row) * DP + cc * 8;              \
                uint32_t dst = bb + (row * SKW + cc * 8) * 2;                     \
                cp16(dst, src);                                                   \
            }                                                                     \
        }                                                                         \
    } while (0)

    // PV B-fragment load for one kc2 slice into pb[18]
    #define PV_LDSM(KC2)                                                          \
    do {                                                                          \
        _Pragma("unroll")                                                         \
        for (int dn2 = 0; dn2 < 4; dn2++) {                                       \
            uint32_t off = (16 * (KC2) * SKW + 16 * dn2) * 2 + pv_off;            \
            LDSM4T(pb[4*dn2], pb[4*dn2+1], pb[4*dn2+2], pb[4*dn2+3], sX + off);   \
        }                                                                         \
        {                                                                         \
            uint32_t off = (16 * (KC2) * SKW) * 2 + pv2_off;                      \
            LDSM2T(pb[16], pb[17], sX + off);                                     \
        }                                                                         \
    } while (0)

    PREFETCH(chLo); cpcommit();
    if (chLo + 1 < chHi) PREFETCH(chLo + 1);
    cpcommit();

    for (int ch = chLo; ch < chHi; ch++) {
        if (ch + 2 < chHi) PREFETCH(ch + 2);
        cpcommit();
        cpwait2();
        __syncthreads();

        const uint32_t sX = sbase + (ch & (NBUF - 1)) * ABYTES;

        // ---- QK: S(log2) = q' . X  (single pass) ----
        float s[2][8][4];
        #pragma unroll
        for (int mt = 0; mt < 2; mt++)
            #pragma unroll
            for (int i = 0; i < 8; i++)
                #pragma unroll
                for (int c = 0; c < 4; c++) s[mt][i][c] = 0.0f;

        #pragma unroll
        for (int kc = 0; kc < 4; kc++) {
            #pragma unroll
            for (int jn2 = 0; jn2 < 4; jn2++) {
                uint32_t off = (16 * jn2 * SKW + 16 * kc) * 2 + qk_off;
                uint32_t b0, b1, b2, b3;
                LDSM4(b0, b1, b2, b3, sX + off);
                #pragma unroll
                for (int mt = 0; mt < 2; mt++) {
                    MMA16(s[mt][2 * jn2],     aq[mt][kc], b0, b1);
                    MMA16(s[mt][2 * jn2 + 1], aq[mt][kc], b2, b3);
                }
            }
        }
        #pragma unroll
        for (int jn2 = 0; jn2 < 4; jn2++) {
            uint32_t off = (16 * jn2 * SKW) * 2 + qk8_off;
            uint32_t b0, b1;
            LDSM2(b0, b1, sX + off);
            #pragma unroll
            for (int mt = 0; mt < 2; mt++) {
                MMA8(s[mt][2 * jn2],     aq8[mt][0], aq8[mt][1], b0);
                MMA8(s[mt][2 * jn2 + 1], aq8[mt][0], aq8[mt][1], b1);
            }
        }

        // ---- preload PV slice 0 fragments (LSU hides under reduce) ----
        uint32_t pb[18];
        PV_LDSM(0);

        // ---- online softmax (exact): reduce, rescale-if-needed ----
        float mN[4];
        {
            float mx0 = -1e30f, mx1 = -1e30f, mx2 = -1e30f, mx3 = -1e30f;
            #pragma unroll
            for (int i = 0; i < 8; i++) {
                mx0 = fmaxf(mx0, fmaxf(s[0][i][0], s[0][i][1]));
                mx1 = fmaxf(mx1, fmaxf(s[0][i][2], s[0][i][3]));
                mx2 = fmaxf(mx2, fmaxf(s[1][i][0], s[1][i][1]));
                mx3 = fmaxf(mx3, fmaxf(s[1][i][2], s[1][i][3]));
            }
            mx0 = fmaxf(mx0, __shfl_xor_sync(0xffffffffu, mx0, 1));
            mx1 = fmaxf(mx1, __shfl_xor_sync(0xffffffffu, mx1, 1));
            mx2 = fmaxf(mx2, __shfl_xor_sync(0xffffffffu, mx2, 1));
            mx3 = fmaxf(mx3, __shfl_xor_sync(0xffffffffu, mx3, 1));
            mx0 = fmaxf(mx0, __shfl_xor_sync(0xffffffffu, mx0, 2));
            mx1 = fmaxf(mx1, __shfl_xor_sync(0xffffffffu, mx1, 2));
            mx2 = fmaxf(mx2, __shfl_xor_sync(0xffffffffu, mx2, 2));
            mx3 = fmaxf(mx3, __shfl_xor_sync(0xffffffffu, mx3, 2));
            mN[0] = fmaxf(m[0], mx0);
            mN[1] = fmaxf(m[1], mx1);
            mN[2] = fmaxf(m[2], mx2);
            mN[3] = fmaxf(m[3], mx3);
            bool nochg = (mN[0] == m[0]) & (mN[1] == m[1]) &
                         (mN[2] == m[2]) & (mN[3] == m[3]);
            if (!__all_sync(0xffffffffu, nochg)) {
                float a0 = exp2f(m[0] - mN[0]);
                float a1 = exp2f(m[1] - mN[1]);
                float a2 = exp2f(m[2] - mN[2]);
                float a3 = exp2f(m[3] - mN[3]);
                l[0] *= a0; l[1] *= a1; l[2] *= a2; l[3] *= a3;
                #pragma unroll
                for (int i = 0; i < 9; i++) {
                    o[0][i][0] *= a0; o[0][i][1] *= a0;
                    o[0][i][2] *= a1; o[0][i][3] *= a1;
                    o[1][i][0] *= a2; o[1][i][1] *= a2;
                    o[1][i][2] *= a3; o[1][i][3] *= a3;
                }
                m[0] = mN[0]; m[1] = mN[1]; m[2] = mN[2]; m[3] = mN[3];
            }
        }

        // ---- per-kc2 pipeline: exp -> PV MMA -> l-accum -> next LDSM ----
        __half2 lA2 = __floats2half2_rn(0.f, 0.f);
        __half2 lB2 = __floats2half2_rn(0.f, 0.f);
        __half2 lC2 = __floats2half2_rn(0.f, 0.f);
        __half2 lD2 = __floats2half2_rn(0.f, 0.f);
        #pragma unroll
        for (int u = 0; u < 4; u++) {
            uint32_t p0[4], p1[4];
            p0[0] = ex2h2(pack2h(s[0][2*u][0]   - mN[0], s[0][2*u][1]   - mN[0]));
            p0[1] = ex2h2(pack2h(s[0][2*u][2]   - mN[1], s[0][2*u][3]   - mN[1]));
            p0[2] = ex2h2(pack2h(s[0][2*u+1][0] - mN[0], s[0][2*u+1][1] - mN[0]));
            p0[3] = ex2h2(pack2h(s[0][2*u+1][2] - mN[1], s[0][2*u+1][3] - mN[1]));
            p1[0] = ex2h2(pack2h(s[1][2*u][0]   - mN[2], s[1][2*u][1]   - mN[2]));
            p1[1] = ex2h2(pack2h(s[1][2*u][2]   - mN[3], s[1][2*u][3]   - mN[3]));
            p1[2] = ex2h2(pack2h(s[1][2*u+1][0] - mN[2], s[1][2*u+1][1] - mN[2]));
            p1[3] = ex2h2(pack2h(s[1][2*u+1][2] - mN[3], s[1][2*u+1][3] - mN[3]));

            #pragma unroll
            for (int dn2 = 0; dn2 < 4; dn2++) {
                MMA16(o[0][2 * dn2],     p0, pb[4*dn2],   pb[4*dn2+1]);
                MMA16(o[0][2 * dn2 + 1], p0, pb[4*dn2+2], pb[4*dn2+3]);
                MMA16(o[1][2 * dn2],     p1, pb[4*dn2],   pb[4*dn2+1]);
                MMA16(o[1][2 * dn2 + 1], p1, pb[4*dn2+2], pb[4*dn2+3]);
            }
            MMA16(o[0][8], p0, pb[16], pb[17]);
            MMA16(o[1][8], p1, pb[16], pb[17]);

            lA2 = __hadd2(lA2, h2(p0[0])); lA2 = __hadd2(lA2, h2(p0[2]));
            lB2 = __hadd2(lB2, h2(p0[1])); lB2 = __hadd2(lB2, h2(p0[3]));
            lC2 = __hadd2(lC2, h2(p1[0])); lC2 = __hadd2(lC2, h2(p1[2]));
            lD2 = __hadd2(lD2, h2(p1[1])); lD2 = __hadd2(lD2, h2(p1[3]));

            if (u < 3) PV_LDSM(u + 1);
        }
        {
            float2 va = __half22float2(lA2);
            float2 vb = __half22float2(lB2);
            float2 vc = __half22float2(lC2);
            float2 vd = __half22float2(lD2);
            l[0] += va.x + va.y;
            l[1] += vb.x + vb.y;
            l[2] += vc.x + vc.y;
            l[3] += vd.x + vd.y;
        }
        // no trailing sync: ring-of-4 + distance-2 prefetch keeps the live
        // buffer safe (all warps passed this iteration's barrier).
    }

    // ---- epilogue ----
    #pragma unroll
    for (int i = 0; i < 4; i++) {
        l[i] += __shfl_xor_sync(0xffffffffu, l[i], 1);
        l[i] += __shfl_xor_sync(0xffffffffu, l[i], 2);
    }
    if ((lane & 3) == 0) {
        #pragma unroll
        for (int mt = 0; mt < 2; mt++) {
            g_ml[split * NQT + q0w + 16 * mt + g]     = make_float2(m[2*mt],   l[2*mt]);
            g_ml[split * NQT + q0w + 16 * mt + g + 8] = make_float2(m[2*mt+1], l[2*mt+1]);
        }
    }
    const size_t ob = (size_t)split * NQT;
    #pragma unroll
    for (int mt = 0; mt < 2; mt++) {
        #pragma unroll
        for (int dn = 0; dn < 9; dn++) {
            int d0 = 8 * dn + 2 * t;
            if (d0 < D66) {
                *(float2*)(g_part + (ob + q0w + 16*mt + g)     * D66 + d0) =
                    make_float2(o[mt][dn][0], o[mt][dn][1]);
                *(float2*)(g_part + (ob + q0w + 16*mt + g + 8) * D66 + d0) =
                    make_float2(o[mt][dn][2], o[mt][dn][3]);
            }
        }
    }
}

// ============================================================
// Kernel 3: combine — 8 threads/query, LSE merge over 9 (log2 units)
// ============================================================
__global__ void __launch_bounds__(256)
combine_kernel(float* __restrict__ out) {
    const int tid = threadIdx.x;
    const int part = tid & 7;
    const int q = blockIdx.x * 32 + (tid >> 3);

    float M = -1e30f;
    float mx[SPLITS], lx[SPLITS];
    #pragma unroll
    for (int s = 0; s < SPLITS; s++) {
        float2 v = g_ml[s * NQT + q];
        mx[s] = v.x; lx[s] = v.y;
        M = fmaxf(M, v.x);
    }
    float wgt[SPLITS];
    float l = 0.0f;
    #pragma unroll
    for (int s = 0; s < SPLITS; s++) {
        wgt[s] = exp2f(mx[s] - M);
        l += wgt[s] * lx[s];
    }
    float inv = 1.0f / l;

    #pragma unroll
    for (int i = 0; i < 5; i++) {
        int pr = part * 5 + i;          // d-pair index, 0..39
        if (pr < 33) {
            float ax = 0.0f, ay = 0.0f;
            #pragma unroll
            for (int s = 0; s < SPLITS; s++) {
                float2 v = *(const float2*)(g_part + ((size_t)s * NQT + q) * D66 + 2 * pr);
                ax = fmaf(wgt[s], v.x, ax);
                ay = fmaf(wgt[s], v.y, ay);
            }
            out[(size_t)q * D66 + 2 * pr]     = ax * inv;
            out[(size_t)q * D66 + 2 * pr + 1] = ay * inv;
        }
    }
}

// ============================================================
extern "C" void kernel_launch(void* const* d_in, const int* in_sizes, int n_in,
                              void* d_out, int out_size) {
    const float* x     = (const float*)d_in[0];
    const float* query = (const float*)d_in[1];
    const float* Wk    = (const float*)d_in[2];
    // bk unused: q.b cancels in softmax
    float* out = (float*)d_out;

    const int smem_bytes = NBUF * ABYTES;   // 36864
    cudaFuncSetAttribute(flash_kernel,
                         cudaFuncAttributeMaxDynamicSharedMemorySize, smem_bytes);

    qprime_kernel<<<NQT / 128, 128>>>(query, Wk);
    xsplit_kernel<<<NK / 256, 256>>>(x);
    flash_kernel<<<64 * SPLITS, 128, smem_bytes>>>();
    combine_kernel<<<NQT / 32, 256>>>(out);
}

// round 16
// speedup vs baseline: 1.3699x; 1.0599x over previous
#include <cuda_runtime.h>
#include <cuda_fp16.h>
#include <cstdint>

#define D66     66
#define DP      72                 // padded dim (4x k16 + 1x k8)
#define NK      65536
#define NQT     8192
#define SPLITS  9
#define NCHALL  (NK / 64)          // 1024 total chunks
#define CK      64
#define SKW     72                 // smem row pitch (fp16); 144B rows
#define ABYTES  (CK * SKW * 2)     // 9216 = one chunk buffer
#define NBUF    4
#define NGROUPS (CK * 9)           // 576 16B-groups per chunk

// static device scratch (no cudaMalloc)
__device__ __align__(16) __half g_xh[(size_t)NK * DP];        // fp16(x)
__device__ __align__(16) __half g_qp[(size_t)NQT * DP];       // fp16(L2E*q')
__device__ float  g_part[(size_t)SPLITS * NQT * D66];
__device__ float2 g_ml[SPLITS * NQT];

// ---------------- asm helpers ----------------
#define MMA16(dv, av, b0_, b1_)                                             \
    asm volatile("mma.sync.aligned.m16n8k16.row.col.f32.f16.f16.f32 "       \
                 "{%0,%1,%2,%3},{%4,%5,%6,%7},{%8,%9},{%0,%1,%2,%3};"       \
                 : "+f"(dv[0]), "+f"(dv[1]), "+f"(dv[2]), "+f"(dv[3])       \
                 : "r"(av[0]), "r"(av[1]), "r"(av[2]), "r"(av[3]),          \
                   "r"(b0_), "r"(b1_))

#define MMA8(dv, a0_, a1_, b0_)                                             \
    asm volatile("mma.sync.aligned.m16n8k8.row.col.f32.f16.f16.f32 "        \
                 "{%0,%1,%2,%3},{%4,%5},{%6},{%0,%1,%2,%3};"                \
                 : "+f"(dv[0]), "+f"(dv[1]), "+f"(dv[2]), "+f"(dv[3])       \
                 : "r"(a0_), "r"(a1_), "r"(b0_))

#define LDSM4(r0, r1, r2, r3, ad)                                           \
    asm volatile("ldmatrix.sync.aligned.m8n8.x4.shared.b16 {%0,%1,%2,%3},[%4];" \
                 : "=r"(r0), "=r"(r1), "=r"(r2), "=r"(r3) : "r"(ad))

#define LDSM2(r0, r1, ad)                                                   \
    asm volatile("ldmatrix.sync.aligned.m8n8.x2.shared.b16 {%0,%1},[%2];"   \
                 : "=r"(r0), "=r"(r1) : "r"(ad))

#define LDSM4T(r0, r1, r2, r3, ad)                                          \
    asm volatile("ldmatrix.sync.aligned.m8n8.x4.trans.shared.b16 {%0,%1,%2,%3},[%4];" \
                 : "=r"(r0), "=r"(r1), "=r"(r2), "=r"(r3) : "r"(ad))

#define LDSM2T(r0, r1, ad)                                                  \
    asm volatile("ldmatrix.sync.aligned.m8n8.x2.trans.shared.b16 {%0,%1},[%2];" \
                 : "=r"(r0), "=r"(r1) : "r"(ad))

__device__ __forceinline__ void cp16(uint32_t dst, const void* src) {
    asm volatile("cp.async.cg.shared.global [%0],[%1],16;" :: "r"(dst), "l"(src));
}
__device__ __forceinline__ void cpcommit() { asm volatile("cp.async.commit_group;"); }
__device__ __forceinline__ void cpwait0()  { asm volatile("cp.async.wait_group 0;"); }

__device__ __forceinline__ uint32_t pack2h(float x, float y) {
    __half2 h = __floats2half2_rn(x, y);
    return *reinterpret_cast<uint32_t*>(&h);
}
__device__ __forceinline__ uint32_t ex2h2(uint32_t a) {
    uint32_t d;
    asm("ex2.approx.f16x2 %0, %1;" : "=r"(d) : "r"(a));
    return d;
}
__device__ __forceinline__ __half2 h2(uint32_t a) {
    return *reinterpret_cast<__half2*>(&a);
}

#define L2E 1.44269504f

// ============================================================
// Kernel 1a: q' = fp16(L2E * Wk^T q) — 64 rows x 2 j-halves/block
// ============================================================
__global__ void __launch_bounds__(128)
qprime_kernel(const float* __restrict__ query, const float* __restrict__ Wk) {
    __shared__ float sW[D66 * D66];
    const int tid  = threadIdx.x;
    const int row  = blockIdx.x * 64 + (tid & 63);
    const int half = tid >> 6;                    // 0 or 1
    for (int i = tid; i < D66 * D66; i += 128) sW[i] = Wk[i];
    __syncthreads();

    float qr[D66];
    const float2* qp = (const float2*)(query + (size_t)row * D66);
    #pragma unroll
    for (int c = 0; c < 33; c++) { float2 v = qp[c]; qr[2*c] = v.x; qr[2*c+1] = v.y; }

    const size_t rb = (size_t)row * DP;
    const int jp0 = half ? 17 : 0;
    const int jp1 = half ? 33 : 17;

    #pragma unroll 1
    for (int jp = jp0; jp < jp1; jp++) {
        int j = 2 * jp;
        float a0 = 0.0f, a1 = 0.0f;
        #pragma unroll
        for (int d = 0; d < D66; d++) {
            a0 = fmaf(qr[d], sW[d * D66 + j], a0);
            a1 = fmaf(qr[d], sW[d * D66 + j + 1], a1);
        }
        *(uint32_t*)(g_qp + rb + j) = pack2h(a0 * L2E, a1 * L2E);
    }
    if (half) {
        #pragma unroll
        for (int c = 33; c < DP / 2; c++)
            *(uint32_t*)(g_qp + rb + 2 * c) = 0u;
    }
}

// ============================================================
// Kernel 1b: x -> fp16, padded to DP=72
// ============================================================
__global__ void __launch_bounds__(256)
xsplit_kernel(const float* __restrict__ x) {
    const int n = blockIdx.x * 256 + threadIdx.x;
    const size_t rb = (size_t)n * DP;
    const float2* xp = (const float2*)(x + (size_t)n * D66);
    #pragma unroll
    for (int c = 0; c < 33; c++) {
        float2 v = xp[c];
        *(uint32_t*)(g_xh + rb + 2 * c) = pack2h(v.x, v.y);
    }
    #pragma unroll
    for (int c = 33; c < DP / 2; c++)
        *(uint32_t*)(g_xh + rb + 2 * c) = 0u;
}

// ============================================================
// Kernel 2: flash — 1-pass QK, exact online max, PV slice pipeline,
// 2 chunks per barrier (ring-of-4 keeps buffers disjoint).
// ============================================================
extern __shared__ __half smbuf[];

__global__ void __launch_bounds__(128, 2)
flash_kernel() {
    const int tid  = threadIdx.x;
    const int lane = tid & 31;
    const int w    = tid >> 5;
    const int qtile = blockIdx.x % 64;
    const int split = blockIdx.x / 64;          // 0..8
    const int q0w = qtile * 128 + w * 32;
    const int chLo = (split * NCHALL) / SPLITS;
    const int chHi = ((split + 1) * NCHALL) / SPLITS;

    const int g  = lane >> 2;
    const int t  = lane & 3;
    const int q8 = lane >> 3;
    const int r  = lane & 7;

    const uint32_t sbase = (uint32_t)__cvta_generic_to_shared(smbuf);

    // ---- q' fragments (resident; single fp16 copy) ----
    uint32_t aq[2][4][4], aq8[2][2];
    {
        #pragma unroll
        for (int mt = 0; mt < 2; mt++) {
            const size_t r0 = (size_t)(q0w + 16 * mt + g) * DP;
            const size_t r1 = (size_t)(q0w + 16 * mt + g + 8) * DP;
            #pragma unroll
            for (int kc = 0; kc < 4; kc++) {
                int c0 = 16 * kc + 2 * t;
                aq[mt][kc][0] = *(const uint32_t*)(g_qp + r0 + c0);
                aq[mt][kc][1] = *(const uint32_t*)(g_qp + r1 + c0);
                aq[mt][kc][2] = *(const uint32_t*)(g_qp + r0 + c0 + 8);
                aq[mt][kc][3] = *(const uint32_t*)(g_qp + r1 + c0 + 8);
            }
            int c8 = 64 + 2 * t;
            aq8[mt][0] = *(const uint32_t*)(g_qp + r0 + c8);
            aq8[mt][1] = *(const uint32_t*)(g_qp + r1 + c8);
        }
    }

    const uint32_t qk_off  = ((8 * (q8 >> 1) + r) * SKW + 8 * (q8 & 1)) * 2;
    const uint32_t qk8_off = ((8 * (q8 & 1) + r) * SKW + 64) * 2;
    const uint32_t pv_off  = ((8 * (q8 & 1) + r) * SKW + 8 * (q8 >> 1)) * 2;
    const uint32_t pv2_off = ((8 * (q8 & 1) + r) * SKW + 64) * 2;

    float o[2][9][4];
    #pragma unroll
    for (int mt = 0; mt < 2; mt++)
        #pragma unroll
        for (int i = 0; i < 9; i++)
            #pragma unroll
            for (int c = 0; c < 4; c++) o[mt][i][c] = 0.0f;
    float m[4] = {-1e30f, -1e30f, -1e30f, -1e30f};   // log2 units
    float l[4] = {0.0f, 0.0f, 0.0f, 0.0f};

    #define PREFETCH(CH)                                                          \
    do {                                                                          \
        const size_t kb = (size_t)(CH) * CK;                                      \
        const uint32_t bb = sbase + ((CH) & (NBUF - 1)) * ABYTES;                 \
        _Pragma("unroll")                                                         \
        for (int jj = 0; jj < 5; jj++) {                                          \
            int j = tid + jj * 128;                                               \
            if (j < NGROUPS) {                                                    \
                int row = j / 9;                                                  \
                int cc  = j - row * 9;                                            \
                const __half* src = g_xh + (kb + row) * DP + cc * 8;              \
                uint32_t dst = bb + (row * SKW + cc * 8) * 2;                     \
                cp16(dst, src);                                                   \
            }                                                                     \
        }                                                                         \
    } while (0)

    #define PV_LDSM(KC2)                                                          \
    do {                                                                          \
        _Pragma("unroll")                                                         \
        for (int dn2 = 0; dn2 < 4; dn2++) {                                       \
            uint32_t off = (16 * (KC2) * SKW + 16 * dn2) * 2 + pv_off;            \
            LDSM4T(pb[4*dn2], pb[4*dn2+1], pb[4*dn2+2], pb[4*dn2+3], sX + off);   \
        }                                                                         \
        {                                                                         \
            uint32_t off = (16 * (KC2) * SKW) * 2 + pv2_off;                      \
            LDSM2T(pb[16], pb[17], sX + off);                                     \
        }                                                                         \
    } while (0)

    // full per-chunk compute (QK -> softmax -> pipelined PV)
    #define COMPUTE(CH)                                                           \
    do {                                                                          \
        const uint32_t sX = sbase + ((CH) & (NBUF - 1)) * ABYTES;                 \
        float s[2][8][4];                                                         \
        _Pragma("unroll")                                                         \
        for (int mt = 0; mt < 2; mt++)                                            \
            _Pragma("unroll")                                                     \
            for (int i = 0; i < 8; i++)                                           \
                _Pragma("unroll")                                                 \
                for (int c = 0; c < 4; c++) s[mt][i][c] = 0.0f;                   \
        _Pragma("unroll")                                                         \
        for (int kc = 0; kc < 4; kc++) {                                          \
            _Pragma("unroll")                                                     \
            for (int jn2 = 0; jn2 < 4; jn2++) {                                   \
                uint32_t off = (16 * jn2 * SKW + 16 * kc) * 2 + qk_off;           \
                uint32_t b0, b1, b2, b3;                                          \
                LDSM4(b0, b1, b2, b3, sX + off);                                  \
                _Pragma("unroll")                                                 \
                for (int mt = 0; mt < 2; mt++) {                                  \
                    MMA16(s[mt][2 * jn2],     aq[mt][kc], b0, b1);                \
                    MMA16(s[mt][2 * jn2 + 1], aq[mt][kc], b2, b3);                \
                }                                                                 \
            }                                                                     \
        }                                                                         \
        _Pragma("unroll")                                                         \
        for (int jn2 = 0; jn2 < 4; jn2++) {                                       \
            uint32_t off = (16 * jn2 * SKW) * 2 + qk8_off;                        \
            uint32_t b0, b1;                                                      \
            LDSM2(b0, b1, sX + off);                                              \
            _Pragma("unroll")                                                     \
            for (int mt = 0; mt < 2; mt++) {                                      \
                MMA8(s[mt][2 * jn2],     aq8[mt][0], aq8[mt][1], b0);             \
                MMA8(s[mt][2 * jn2 + 1], aq8[mt][0], aq8[mt][1], b1);             \
            }                                                                     \
        }                                                                         \
        uint32_t pb[18];                                                          \
        PV_LDSM(0);                                                               \
        float mN[4];                                                              \
        {                                                                         \
            float mx0 = -1e30f, mx1 = -1e30f, mx2 = -1e30f, mx3 = -1e30f;         \
            _Pragma("unroll")                                                     \
            for (int i = 0; i < 8; i++) {                                         \
                mx0 = fmaxf(mx0, fmaxf(s[0][i][0], s[0][i][1]));                  \
                mx1 = fmaxf(mx1, fmaxf(s[0][i][2], s[0][i][3]));                  \
                mx2 = fmaxf(mx2, fmaxf(s[1][i][0], s[1][i][1]));                  \
                mx3 = fmaxf(mx3, fmaxf(s[1][i][2], s[1][i][3]));                  \
            }                                                                     \
            mx0 = fmaxf(mx0, __shfl_xor_sync(0xffffffffu, mx0, 1));               \
            mx1 = fmaxf(mx1, __shfl_xor_sync(0xffffffffu, mx1, 1));               \
            mx2 = fmaxf(mx2, __shfl_xor_sync(0xffffffffu, mx2, 1));               \
            mx3 = fmaxf(mx3, __shfl_xor_sync(0xffffffffu, mx3, 1));               \
            mx0 = fmaxf(mx0, __shfl_xor_sync(0xffffffffu, mx0, 2));               \
            mx1 = fmaxf(mx1, __shfl_xor_sync(0xffffffffu, mx1, 2));               \
            mx2 = fmaxf(mx2, __shfl_xor_sync(0xffffffffu, mx2, 2));               \
            mx3 = fmaxf(mx3, __shfl_xor_sync(0xffffffffu, mx3, 2));               \
            mN[0] = fmaxf(m[0], mx0);                                             \
            mN[1] = fmaxf(m[1], mx1);                                             \
            mN[2] = fmaxf(m[2], mx2);                                             \
            mN[3] = fmaxf(m[3], mx3);                                             \
            bool nochg = (mN[0] == m[0]) & (mN[1] == m[1]) &                      \
                         (mN[2] == m[2]) & (mN[3] == m[3]);                       \
            if (!__all_sync(0xffffffffu, nochg)) {                                \
                float a0 = exp2f(m[0] - mN[0]);                                   \
                float a1 = exp2f(m[1] - mN[1]);                                   \
                float a2 = exp2f(m[2] - mN[2]);                                   \
                float a3 = exp2f(m[3] - mN[3]);                                   \
                l[0] *= a0; l[1] *= a1; l[2] *= a2; l[3] *= a3;                   \
                _Pragma("unroll")                                                 \
                for (int i = 0; i < 9; i++) {                                     \
                    o[0][i][0] *= a0; o[0][i][1] *= a0;                           \
                    o[0][i][2] *= a1; o[0][i][3] *= a1;                           \
                    o[1][i][0] *= a2; o[1][i][1] *= a2;                           \
                    o[1][i][2] *= a3; o[1][i][3] *= a3;                           \
                }                                                                 \
                m[0] = mN[0]; m[1] = mN[1]; m[2] = mN[2]; m[3] = mN[3];           \
            }                                                                     \
        }                                                                         \
        __half2 lA2 = __floats2half2_rn(0.f, 0.f);                                \
        __half2 lB2 = __floats2half2_rn(0.f, 0.f);                                \
        __half2 lC2 = __floats2half2_rn(0.f, 0.f);                                \
        __half2 lD2 = __floats2half2_rn(0.f, 0.f);                                \
        _Pragma("unroll")                                                         \
        for (int u = 0; u < 4; u++) {                                             \
            uint32_t p0[4], p1[4];                                                \
            p0[0] = ex2h2(pack2h(s[0][2*u][0]   - mN[0], s[0][2*u][1]   - mN[0]));\
            p0[1] = ex2h2(pack2h(s[0][2*u][2]   - mN[1], s[0][2*u][3]   - mN[1]));\
            p0[2] = ex2h2(pack2h(s[0][2*u+1][0] - mN[0], s[0][2*u+1][1] - mN[0]));\
            p0[3] = ex2h2(pack2h(s[0][2*u+1][2] - mN[1], s[0][2*u+1][3] - mN[1]));\
            p1[0] = ex2h2(pack2h(s[1][2*u][0]   - mN[2], s[1][2*u][1]   - mN[2]));\
            p1[1] = ex2h2(pack2h(s[1][2*u][2]   - mN[3], s[1][2*u][3]   - mN[3]));\
            p1[2] = ex2h2(pack2h(s[1][2*u+1][0] - mN[2], s[1][2*u+1][1] - mN[2]));\
            p1[3] = ex2h2(pack2h(s[1][2*u+1][2] - mN[3], s[1][2*u+1][3] - mN[3]));\
            _Pragma("unroll")                                                     \
            for (int dn2 = 0; dn2 < 4; dn2++) {                                   \
                MMA16(o[0][2 * dn2],     p0, pb[4*dn2],   pb[4*dn2+1]);           \
                MMA16(o[0][2 * dn2 + 1], p0, pb[4*dn2+2], pb[4*dn2+3]);           \
                MMA16(o[1][2 * dn2],     p1, pb[4*dn2],   pb[4*dn2+1]);           \
                MMA16(o[1][2 * dn2 + 1], p1, pb[4*dn2+2], pb[4*dn2+3]);           \
            }                                                                     \
            MMA16(o[0][8], p0, pb[16], pb[17]);                                   \
            MMA16(o[1][8], p1, pb[16], pb[17]);                                   \
            lA2 = __hadd2(lA2, h2(p0[0])); lA2 = __hadd2(lA2, h2(p0[2]));         \
            lB2 = __hadd2(lB2, h2(p0[1])); lB2 = __hadd2(lB2, h2(p0[3]));         \
            lC2 = __hadd2(lC2, h2(p1[0])); lC2 = __hadd2(lC2, h2(p1[2]));         \
            lD2 = __hadd2(lD2, h2(p1[1])); lD2 = __hadd2(lD2, h2(p1[3]));         \
            if (u < 3) PV_LDSM(u + 1);                                            \
        }                                                                         \
        {                                                                         \
            float2 va = __half22float2(lA2);                                      \
            float2 vb = __half22float2(lB2);                                      \
            float2 vc = __half22float2(lC2);                                      \
            float2 vd = __half22float2(lD2);                                      \
            l[0] += va.x + va.y;                                                  \
            l[1] += vb.x + vb.y;                                                  \
            l[2] += vc.x + vc.y;                                                  \
            l[3] += vd.x + vd.y;                                                  \
        }                                                                         \
    } while (0)

    // prime: chunks chLo, chLo+1 in one group
    PREFETCH(chLo);
    PREFETCH(chLo + 1);              // chHi-chLo >= 113, always valid
    cpcommit();

    int ch = chLo;
    for (; ch + 1 < chHi; ch += 2) {
        cpwait0();                   // pair [ch, ch+1] landed
        __syncthreads();             // all warps done with old buffers
        if (ch + 2 < chHi) PREFETCH(ch + 2);
        if (ch + 3 < chHi) PREFETCH(ch + 3);
        cpcommit();                  // overlaps the 2 computes below
        COMPUTE(ch);
        COMPUTE(ch + 1);
    }
    if (ch < chHi) {                 // odd leftover chunk
        cpwait0();
        __syncthreads();
        COMPUTE(ch);
    }

    // ---- epilogue ----
    #pragma unroll
    for (int i = 0; i < 4; i++) {
        l[i] += __shfl_xor_sync(0xffffffffu, l[i], 1);
        l[i] += __shfl_xor_sync(0xffffffffu, l[i], 2);
    }
    if ((lane & 3) == 0) {
        #pragma unroll
        for (int mt = 0; mt < 2; mt++) {
            g_ml[split * NQT + q0w + 16 * mt + g]     = make_float2(m[2*mt],   l[2*mt]);
            g_ml[split * NQT + q0w + 16 * mt + g + 8] = make_float2(m[2*mt+1], l[2*mt+1]);
        }
    }
    const size_t ob = (size_t)split * NQT;
    #pragma unroll
    for (int mt = 0; mt < 2; mt++) {
        #pragma unroll
        for (int dn = 0; dn < 9; dn++) {
            int d0 = 8 * dn + 2 * t;
            if (d0 < D66) {
                *(float2*)(g_part + (ob + q0w + 16*mt + g)     * D66 + d0) =
                    make_float2(o[mt][dn][0], o[mt][dn][1]);
                *(float2*)(g_part + (ob + q0w + 16*mt + g + 8) * D66 + d0) =
                    make_float2(o[mt][dn][2], o[mt][dn][3]);
            }
        }
    }
}

// ============================================================
// Kernel 3: combine — 16 threads/query, LSE merge over 9
// ============================================================
__global__ void __launch_bounds__(256)
combine_kernel(float* __restrict__ out) {
    const int tid = threadIdx.x;
    const int part = tid & 15;
    const int q = blockIdx.x * 16 + (tid >> 4);

    float M = -1e30f;
    float mx[SPLITS], lx[SPLITS];
    #pragma unroll
    for (int s = 0; s < SPLITS; s++) {
        float2 v = g_ml[s * NQT + q];
        mx[s] = v.x; lx[s] = v.y;
        M = fmaxf(M, v.x);
    }
    float wgt[SPLITS];
    float l = 0.0f;
    #pragma unroll
    for (int s = 0; s < SPLITS; s++) {
        wgt[s] = exp2f(mx[s] - M);
        l += wgt[s] * lx[s];
    }
    float inv = 1.0f / l;

    #pragma unroll
    for (int i = 0; i < 3; i++) {
        int pr = part + 16 * i;          // d-pair index; coalesced across part
        if (pr < 33) {
            float ax = 0.0f, ay = 0.0f;
            #pragma unroll
            for (int s = 0; s < SPLITS; s++) {
                float2 v = *(const float2*)(g_part + ((size_t)s * NQT + q) * D66 + 2 * pr);
                ax = fmaf(wgt[s], v.x, ax);
                ay = fmaf(wgt[s], v.y, ay);
            }
            out[(size_t)q * D66 + 2 * pr]     = ax * inv;
            out[(size_t)q * D66 + 2 * pr + 1] = ay * inv;
        }
    }
}

// ============================================================
extern "C" void kernel_launch(void* const* d_in, const int* in_sizes, int n_in,
                              void* d_out, int out_size) {
    const float* x     = (const float*)d_in[0];
    const float* query = (const float*)d_in[1];
    const float* Wk    = (const float*)d_in[2];
    // bk unused: q.b cancels in softmax
    float* out = (float*)d_out;

    const int smem_bytes = NBUF * ABYTES;   // 36864
    cudaFuncSetAttribute(flash_kernel,
                         cudaFuncAttributeMaxDynamicSharedMemorySize, smem_bytes);

    qprime_kernel<<<NQT / 64, 128>>>(query, Wk);
    xsplit_kernel<<<NK / 256, 256>>>(x);
    flash_kernel<<<64 * SPLITS, 128, smem_bytes>>>();
    combine_kernel<<<NQT / 16, 256>>>(out);
}